// round 1
// baseline (speedup 1.0000x reference)
#include <cuda_runtime.h>

#define BN 16
#define NC 80
#define GN0 19200
#define GN1 4800
#define GN2 1200
#define NT 25200
#define KMAX 25
#define CAP 8192
#define SCORE_T 0.55f
#define IOU_T 0.5f
#define NEGF (-1e30f)

// Static device scratch (no allocs allowed).
__device__ float g_boxes[BN * NT * 4];        // concat bbox, max(x,0), original corner order
__device__ float g_conf[BN * NT];             // concat conf
__device__ float g_kept_score[BN * NC * KMAX];// per (b,c) kept scores (NEG if invalid)
__device__ float g_kept_box[BN * NC * KMAX * 4];

// ---------------------------------------------------------------------------
// Kernel A: flatten the 3 scales into [B, N] layout, apply max(box, 0)
// ---------------------------------------------------------------------------
__global__ void prep_kernel(const float* __restrict__ bb0, const float* __restrict__ cf0,
                            const float* __restrict__ bb1, const float* __restrict__ cf1,
                            const float* __restrict__ bb2, const float* __restrict__ cf2) {
    int i = blockIdx.x * blockDim.x + threadIdx.x;
    if (i >= BN * NT) return;
    int b = i / NT, n = i % NT;
    const float* bp; const float* cp; int loc;
    if (n < GN0)            { bp = bb0; cp = cf0; loc = b * GN0 + n; }
    else if (n < GN0 + GN1) { bp = bb1; cp = cf1; loc = b * GN1 + (n - GN0); }
    else                    { bp = bb2; cp = cf2; loc = b * GN2 + (n - GN0 - GN1); }
    float4 v = reinterpret_cast<const float4*>(bp)[loc];
    v.x = fmaxf(v.x, 0.f); v.y = fmaxf(v.y, 0.f);
    v.z = fmaxf(v.z, 0.f); v.w = fmaxf(v.w, 0.f);
    reinterpret_cast<float4*>(g_boxes)[i] = v;
    g_conf[i] = cp[loc];
}

// ---------------------------------------------------------------------------
// Kernel B: one block per (batch, class). Compact candidates (score > 0.55)
// into shared memory with canonicalized corners, then 25 greedy NMS rounds.
// ---------------------------------------------------------------------------
extern __shared__ float dsm[];

__global__ void nms_kernel(const float* __restrict__ cl0,
                           const float* __restrict__ cl1,
                           const float* __restrict__ cl2) {
    int bc = blockIdx.x;
    int b = bc / NC, c = bc % NC;
    float* sc  = dsm;
    float* cy0 = dsm + CAP;
    float* cx0 = dsm + 2 * CAP;
    float* cy1 = dsm + 3 * CAP;
    float* cx1 = dsm + 4 * CAP;
    int*   cid = (int*)(dsm + 5 * CAP);

    __shared__ int cnt;
    __shared__ float red_s[256];
    __shared__ int   red_i[256];
    __shared__ float bbx[4];
    __shared__ float s_best;

    int tid = threadIdx.x;
    if (tid == 0) cnt = 0;
    __syncthreads();

    const float* confb = g_conf + (size_t)b * NT;

    // --- compaction ---
    for (int n = tid; n < NT; n += blockDim.x) {
        float cv;
        if (n < GN0)            cv = cl0[(size_t)(b * GN0 + n) * NC + c];
        else if (n < GN0 + GN1) cv = cl1[(size_t)(b * GN1 + (n - GN0)) * NC + c];
        else                    cv = cl2[(size_t)(b * GN2 + (n - GN0 - GN1)) * NC + c];
        float s = __fmul_rn(confb[n], cv);
        if (s > SCORE_T) {
            int p = atomicAdd(&cnt, 1);
            if (p < CAP) {
                float4 v = reinterpret_cast<const float4*>(g_boxes)[(size_t)b * NT + n];
                sc[p] = s;
                cy0[p] = fminf(v.x, v.z); cy1[p] = fmaxf(v.x, v.z);
                cx0[p] = fminf(v.y, v.w); cx1[p] = fmaxf(v.y, v.w);
                cid[p] = n;
            }
        }
    }
    __syncthreads();
    int M = min(cnt, CAP);
    int base = bc * KMAX;

    int k = 0;
    for (; k < KMAX; k++) {
        // --- block argmax over candidates ---
        float ms = NEGF; int mi = -1;
        for (int j = tid; j < M; j += blockDim.x) {
            float s = sc[j];
            if (s > ms) { ms = s; mi = j; }
        }
        red_s[tid] = ms; red_i[tid] = mi;
        __syncthreads();
        for (int off = 128; off > 0; off >>= 1) {
            if (tid < off) {
                if (red_s[tid + off] > red_s[tid]) {
                    red_s[tid] = red_s[tid + off];
                    red_i[tid] = red_i[tid + off];
                }
            }
            __syncthreads();
        }
        if (tid == 0) {
            float bs = red_s[0]; int bi = red_i[0];
            s_best = bs;
            if (bs > SCORE_T) {
                int n = cid[bi];
                g_kept_score[base + k] = bs;
                float4 v = reinterpret_cast<const float4*>(g_boxes)[(size_t)b * NT + n];
                g_kept_box[(size_t)(base + k) * 4 + 0] = v.x;
                g_kept_box[(size_t)(base + k) * 4 + 1] = v.y;
                g_kept_box[(size_t)(base + k) * 4 + 2] = v.z;
                g_kept_box[(size_t)(base + k) * 4 + 3] = v.w;
                bbx[0] = cy0[bi]; bbx[1] = cx0[bi]; bbx[2] = cy1[bi]; bbx[3] = cx1[bi];
                sc[bi] = NEGF;
            }
        }
        __syncthreads();
        if (s_best <= SCORE_T) break;

        // --- suppression (exact reference arithmetic order, no fmad) ---
        float by0 = bbx[0], bx0 = bbx[1], by1 = bbx[2], bx1 = bbx[3];
        float a1 = __fmul_rn(__fsub_rn(by1, by0), __fsub_rn(bx1, bx0));
        for (int j = tid; j < M; j += blockDim.x) {
            if (sc[j] > NEGF) {
                float ih = fmaxf(__fsub_rn(fminf(by1, cy1[j]), fmaxf(by0, cy0[j])), 0.f);
                float iw = fmaxf(__fsub_rn(fminf(bx1, cx1[j]), fmaxf(bx0, cx0[j])), 0.f);
                float inter = __fmul_rn(ih, iw);
                float a2 = __fmul_rn(__fsub_rn(cy1[j], cy0[j]), __fsub_rn(cx1[j], cx0[j]));
                float un = __fsub_rn(__fadd_rn(a1, a2), inter);
                if (un > 0.f) {
                    float iou = __fdiv_rn(inter, un);
                    if (iou > IOU_T) sc[j] = NEGF;
                }
            }
        }
        __syncthreads();
    }
    // fill remaining invalid slots
    for (int kk = k + tid; kk < KMAX; kk += blockDim.x) g_kept_score[base + kk] = NEGF;
}

// ---------------------------------------------------------------------------
// Kernel C: per-batch top-25 over [C*K] scores, emit concatenated outputs:
// boxes [B,25,4] | scores [B,25] | cls [B,25] | valid_det [B]  (all float32)
// ---------------------------------------------------------------------------
__global__ void topk_kernel(float* __restrict__ out) {
    int b = blockIdx.x;
    int tid = threadIdx.x;
    __shared__ float s[NC * KMAX];
    __shared__ float red_s[256];
    __shared__ int   red_i[256];
    __shared__ int cnt;

    for (int j = tid; j < NC * KMAX; j += blockDim.x)
        s[j] = g_kept_score[(size_t)b * NC * KMAX + j];
    if (tid == 0) cnt = 0;
    __syncthreads();

    for (int k = 0; k < KMAX; k++) {
        float ms = NEGF; int mi = 0x7fffffff;
        for (int j = tid; j < NC * KMAX; j += blockDim.x) {
            float v = s[j];
            if (v > ms || (v == ms && j < mi)) { ms = v; mi = j; }
        }
        red_s[tid] = ms; red_i[tid] = mi;
        __syncthreads();
        for (int off = 128; off > 0; off >>= 1) {
            if (tid < off) {
                float so = red_s[tid + off]; int io = red_i[tid + off];
                if (so > red_s[tid] || (so == red_s[tid] && io < red_i[tid])) {
                    red_s[tid] = so; red_i[tid] = io;
                }
            }
            __syncthreads();
        }
        if (tid == 0) {
            float ms0 = red_s[0]; int mi0 = red_i[0];
            bool valid = ms0 > SCORE_T;
            out[BN * KMAX * 4 + b * KMAX + k] = valid ? ms0 : 0.f;                  // scores
            out[BN * KMAX * 5 + b * KMAX + k] = valid ? (float)(mi0 / KMAX) : 0.f;  // class id
            #pragma unroll
            for (int j = 0; j < 4; j++) {
                float bv = g_kept_box[((size_t)b * NC * KMAX + mi0) * 4 + j];
                out[((size_t)b * KMAX + k) * 4 + j] = valid ? fminf(fmaxf(bv, 0.f), 1.f) : 0.f;
            }
            s[mi0] = NEGF;
            if (valid) cnt++;
        }
        __syncthreads();
    }
    if (tid == 0) out[BN * KMAX * 6 + b] = (float)cnt;  // valid_det at offset 2400
}

// ---------------------------------------------------------------------------
extern "C" void kernel_launch(void* const* d_in, const int* in_sizes, int n_in,
                              void* d_out, int out_size) {
    const float* bb0 = (const float*)d_in[0];
    const float* cf0 = (const float*)d_in[1];
    const float* cl0 = (const float*)d_in[2];
    const float* bb1 = (const float*)d_in[3];
    const float* cf1 = (const float*)d_in[4];
    const float* cl1 = (const float*)d_in[5];
    const float* bb2 = (const float*)d_in[6];
    const float* cf2 = (const float*)d_in[7];
    const float* cl2 = (const float*)d_in[8];

    // 196608 B dynamic smem: opt-in above the 48KB default (idempotent, capture-safe).
    cudaFuncSetAttribute(nms_kernel, cudaFuncAttributeMaxDynamicSharedMemorySize, 6 * CAP * 4);

    prep_kernel<<<(BN * NT + 255) / 256, 256>>>(bb0, cf0, bb1, cf1, bb2, cf2);
    nms_kernel<<<BN * NC, 256, 6 * CAP * 4>>>(cl0, cl1, cl2);
    topk_kernel<<<BN, 256>>>((float*)d_out);
}

// round 3
// speedup vs baseline: 1.5615x; 1.5615x over previous
#include <cuda_runtime.h>

#define BN 16
#define NC 80
#define GN0 19200
#define GN1 4800
#define GN2 1200
#define NT 25200
#define KMAX 25
#define CAP 3584
#define SCORE_T 0.55f
#define IOU_T 0.5f
#define NEGF (-1e30f)
#define NCELL (BN * NC)

// Static device scratch (no allocs allowed).
__device__ float g_boxes[BN * NT * 4];          // [B,N] boxes, max(x,0), original corner order
__device__ int   g_cnt[NCELL];                  // per-(b,c) candidate counts
__device__ float g_cs[(size_t)NCELL * CAP];     // per-(b,c) candidate scores
__device__ int   g_cn[(size_t)NCELL * CAP];     // per-(b,c) candidate anchor ids
__device__ float g_kept_score[NCELL * KMAX];    // per (b,c) kept scores (NEG if invalid)
__device__ float g_kept_box[NCELL * KMAX * 4];

// ---------------------------------------------------------------------------
// Kernel 0: zero the candidate counters (graph-safe, no memset API needed)
// ---------------------------------------------------------------------------
__global__ void zero_kernel() {
    int i = blockIdx.x * blockDim.x + threadIdx.x;
    if (i < NCELL) g_cnt[i] = 0;
}

// ---------------------------------------------------------------------------
// Kernel 1: fused prep + compaction. One thread per (b, n, c); consecutive
// threads cover consecutive classes -> coalesced cls reads. Winners scatter
// (score, n) into per-(b,c) lists. c==0 thread also writes the prepped box.
// ---------------------------------------------------------------------------
__global__ void compact_kernel(const float* __restrict__ bb0, const float* __restrict__ cf0,
                               const float* __restrict__ cl0,
                               const float* __restrict__ bb1, const float* __restrict__ cf1,
                               const float* __restrict__ cl1,
                               const float* __restrict__ bb2, const float* __restrict__ cf2,
                               const float* __restrict__ cl2) {
    int i = blockIdx.x * blockDim.x + threadIdx.x;
    if (i >= BN * NT * NC) return;
    int c  = i % NC;
    int bn = i / NC;            // b*NT + n
    int n  = bn % NT;
    int b  = bn / NT;

    const float* cl; const float* cf; const float* bp; int loc;
    if (n < GN0)            { cl = cl0; cf = cf0; bp = bb0; loc = b * GN0 + n; }
    else if (n < GN0 + GN1) { cl = cl1; cf = cf1; bp = bb1; loc = b * GN1 + (n - GN0); }
    else                    { cl = cl2; cf = cf2; bp = bb2; loc = b * GN2 + (n - GN0 - GN1); }

    if (c == 0) {
        float4 v = reinterpret_cast<const float4*>(bp)[loc];
        v.x = fmaxf(v.x, 0.f); v.y = fmaxf(v.y, 0.f);
        v.z = fmaxf(v.z, 0.f); v.w = fmaxf(v.w, 0.f);
        reinterpret_cast<float4*>(g_boxes)[bn] = v;
    }

    float s = __fmul_rn(__ldg(cf + loc), cl[(size_t)loc * NC + c]);
    if (s > SCORE_T) {
        int cell = b * NC + c;
        int p = atomicAdd(&g_cnt[cell], 1);
        if (p < CAP) {
            g_cs[(size_t)cell * CAP + p] = s;
            g_cn[(size_t)cell * CAP + p] = n;
        }
    }
}

// ---------------------------------------------------------------------------
// Kernel 2: one block (128 thr) per (batch, class). Load compacted candidates
// into smem (original corners), then 25 greedy NMS rounds with shuffle argmax.
// ---------------------------------------------------------------------------
extern __shared__ float dsm[];

__global__ void __launch_bounds__(128) nms_kernel() {
    int bc = blockIdx.x;
    int b  = bc / NC;
    int tid = threadIdx.x;

    float* sc  = dsm;
    float* ry0 = dsm + CAP;
    float* rx0 = dsm + 2 * CAP;
    float* ry1 = dsm + 3 * CAP;
    float* rx1 = dsm + 4 * CAP;

    __shared__ float wred_s[4];
    __shared__ int   wred_i[4];
    __shared__ float pick[5];   // canonical y0,x0,y1,x1, best-score

    int M = min(g_cnt[bc], CAP);
    const float* cs = g_cs + (size_t)bc * CAP;
    const int*   cn = g_cn + (size_t)bc * CAP;

    for (int j = tid; j < M; j += 128) {
        sc[j] = cs[j];
        float4 v = reinterpret_cast<const float4*>(g_boxes)[b * NT + cn[j]];
        ry0[j] = v.x; rx0[j] = v.y; ry1[j] = v.z; rx1[j] = v.w;
    }
    __syncthreads();

    int base = bc * KMAX;
    int k = 0;
    for (; k < KMAX; k++) {
        // argmax with first-index tiebreak (matches jnp.argmax)
        float ms = NEGF; int mi = 0x7FFFFFFF;
        for (int j = tid; j < M; j += 128) {
            float s = sc[j];
            if (s > ms) { ms = s; mi = j; }   // ascending j: strict > keeps lowest tied j
        }
        #pragma unroll
        for (int o = 16; o; o >>= 1) {
            float os = __shfl_down_sync(0xffffffffu, ms, o);
            int   oi = __shfl_down_sync(0xffffffffu, mi, o);
            if (os > ms || (os == ms && oi < mi)) { ms = os; mi = oi; }
        }
        if ((tid & 31) == 0) { wred_s[tid >> 5] = ms; wred_i[tid >> 5] = mi; }
        __syncthreads();
        if (tid == 0) {
            ms = wred_s[0]; mi = wred_i[0];
            #pragma unroll
            for (int w = 1; w < 4; w++) {
                float os = wred_s[w]; int oi = wred_i[w];
                if (os > ms || (os == ms && oi < mi)) { ms = os; mi = oi; }
            }
            pick[4] = ms;
            if (ms > SCORE_T) {
                g_kept_score[base + k] = ms;
                float a = ry0[mi], bb = rx0[mi], cc = ry1[mi], d = rx1[mi];
                g_kept_box[(base + k) * 4 + 0] = a;
                g_kept_box[(base + k) * 4 + 1] = bb;
                g_kept_box[(base + k) * 4 + 2] = cc;
                g_kept_box[(base + k) * 4 + 3] = d;
                pick[0] = fminf(a, cc);  pick[2] = fmaxf(a, cc);
                pick[1] = fminf(bb, d);  pick[3] = fmaxf(bb, d);
                sc[mi] = NEGF;
            }
        }
        __syncthreads();
        if (pick[4] <= SCORE_T) break;

        // suppression: exact reference arithmetic order, no fmad contraction
        float by0 = pick[0], bx0 = pick[1], by1 = pick[2], bx1 = pick[3];
        float a1 = __fmul_rn(__fsub_rn(by1, by0), __fsub_rn(bx1, bx0));
        for (int j = tid; j < M; j += 128) {
            if (sc[j] > NEGF) {
                float oy0 = ry0[j], ox0 = rx0[j], oy1 = ry1[j], ox1 = rx1[j];
                float y0 = fminf(oy0, oy1), y1 = fmaxf(oy0, oy1);
                float x0 = fminf(ox0, ox1), x1 = fmaxf(ox0, ox1);
                float ih = fmaxf(__fsub_rn(fminf(by1, y1), fmaxf(by0, y0)), 0.f);
                float iw = fmaxf(__fsub_rn(fminf(bx1, x1), fmaxf(bx0, x0)), 0.f);
                float inter = __fmul_rn(ih, iw);
                float a2 = __fmul_rn(__fsub_rn(y1, y0), __fsub_rn(x1, x0));
                float un = __fsub_rn(__fadd_rn(a1, a2), inter);
                if (un > 0.f && __fdiv_rn(inter, un) > IOU_T) sc[j] = NEGF;
            }
        }
        __syncthreads();
    }
    for (int kk = k + tid; kk < KMAX; kk += 128) g_kept_score[base + kk] = NEGF;
}

// ---------------------------------------------------------------------------
// Kernel 3: per-batch top-25 over [C*K] scores, emit concatenated outputs:
// boxes [B,25,4] | scores [B,25] | cls [B,25] | valid_det [B]  (all float32)
// ---------------------------------------------------------------------------
__global__ void topk_kernel(float* __restrict__ out) {
    int b = blockIdx.x;
    int tid = threadIdx.x;
    __shared__ float s[NC * KMAX];
    __shared__ float red_s[256];
    __shared__ int   red_i[256];
    __shared__ int cnt;

    for (int j = tid; j < NC * KMAX; j += blockDim.x)
        s[j] = g_kept_score[b * NC * KMAX + j];
    if (tid == 0) cnt = 0;
    __syncthreads();

    for (int k = 0; k < KMAX; k++) {
        float ms = NEGF; int mi = 0x7fffffff;
        for (int j = tid; j < NC * KMAX; j += blockDim.x) {
            float v = s[j];
            if (v > ms || (v == ms && j < mi)) { ms = v; mi = j; }
        }
        red_s[tid] = ms; red_i[tid] = mi;
        __syncthreads();
        for (int off = 128; off > 0; off >>= 1) {
            if (tid < off) {
                float so = red_s[tid + off]; int io = red_i[tid + off];
                if (so > red_s[tid] || (so == red_s[tid] && io < red_i[tid])) {
                    red_s[tid] = so; red_i[tid] = io;
                }
            }
            __syncthreads();
        }
        if (tid == 0) {
            float ms0 = red_s[0]; int mi0 = red_i[0];
            bool valid = ms0 > SCORE_T;
            out[BN * KMAX * 4 + b * KMAX + k] = valid ? ms0 : 0.f;                  // scores
            out[BN * KMAX * 5 + b * KMAX + k] = valid ? (float)(mi0 / KMAX) : 0.f;  // class id
            #pragma unroll
            for (int j = 0; j < 4; j++) {
                float bv = g_kept_box[(b * NC * KMAX + mi0) * 4 + j];
                out[(b * KMAX + k) * 4 + j] = valid ? fminf(fmaxf(bv, 0.f), 1.f) : 0.f;
            }
            s[mi0] = NEGF;
            if (valid) cnt++;
        }
        __syncthreads();
    }
    if (tid == 0) out[BN * KMAX * 6 + b] = (float)cnt;  // valid_det at offset 2400
}

// ---------------------------------------------------------------------------
extern "C" void kernel_launch(void* const* d_in, const int* in_sizes, int n_in,
                              void* d_out, int out_size) {
    const float* bb0 = (const float*)d_in[0];
    const float* cf0 = (const float*)d_in[1];
    const float* cl0 = (const float*)d_in[2];
    const float* bb1 = (const float*)d_in[3];
    const float* cf1 = (const float*)d_in[4];
    const float* cl1 = (const float*)d_in[5];
    const float* bb2 = (const float*)d_in[6];
    const float* cf2 = (const float*)d_in[7];
    const float* cl2 = (const float*)d_in[8];

    // 71680 B dynamic smem: opt-in above the 48KB default (idempotent, capture-safe).
    cudaFuncSetAttribute(nms_kernel, cudaFuncAttributeMaxDynamicSharedMemorySize, 5 * CAP * 4);

    zero_kernel<<<(NCELL + 255) / 256, 256>>>();
    compact_kernel<<<(BN * NT * NC + 255) / 256, 256>>>(bb0, cf0, cl0, bb1, cf1, cl1,
                                                        bb2, cf2, cl2);
    nms_kernel<<<NCELL, 128, 5 * CAP * 4>>>();
    topk_kernel<<<BN, 256>>>((float*)d_out);
}

// round 5
// speedup vs baseline: 8.3457x; 5.3447x over previous
#include <cuda_runtime.h>

#define BN 16
#define NC 80
#define GN0 19200
#define GN1 4800
#define GN2 1200
#define NT 25200
#define KMAX 25
#define CAP 3584
#define SCORE_T 0.55f
#define IOU_T 0.5f
#define NEGF (-1e30f)
#define NCELL (BN * NC)
#define NBIN 1024
#define CHUNK 768
#define NGRP (CHUNK / 32)
#define CA 64          // anchors per compact block
#define SCAP 24        // smem staging slots per class per compact block

// Static device scratch (zero-initialized at load; g_cnt re-zeroed by topk each run).
__device__ int    g_cnt[NCELL];
__device__ float  g_cs[(size_t)NCELL * CAP];
__device__ float4 g_cbox[(size_t)NCELL * CAP];
__device__ float  g_kept_score[NCELL * KMAX];
__device__ float4 g_kept_box4[NCELL * KMAX];

__device__ __forceinline__ int bin_of(float s) {
    int b = (int)((s - SCORE_T) * ((float)NBIN / 0.45f));
    return max(0, min(NBIN - 1, b));
}

// Exact reference-order IoU > 0.5 test (canonical corners both sides).
__device__ __forceinline__ bool iou_gt(float cy0, float cx0, float cy1, float cx1,
                                       float py0, float px0, float py1, float px1) {
    float ih = fmaxf(__fsub_rn(fminf(cy1, py1), fmaxf(cy0, py0)), 0.f);
    float iw = fmaxf(__fsub_rn(fminf(cx1, px1), fmaxf(cx0, px0)), 0.f);
    float inter = __fmul_rn(ih, iw);
    float a1 = __fmul_rn(__fsub_rn(py1, py0), __fsub_rn(px1, px0));
    float a2 = __fmul_rn(__fsub_rn(cy1, cy0), __fsub_rn(cx1, cx0));
    float un = __fsub_rn(__fadd_rn(a1, a2), inter);
    return (un > 0.f) && (__fdiv_rn(inter, un) > IOU_T);
}

// Warp argmax of (v, i), lowest-index tiebreak; result broadcast to all lanes.
__device__ __forceinline__ void argmax32(float& v, int& i) {
    #pragma unroll
    for (int o = 16; o; o >>= 1) {
        float ov = __shfl_down_sync(0xffffffffu, v, o);
        int   oi = __shfl_down_sync(0xffffffffu, i, o);
        if (ov > v || (ov == v && oi < i)) { v = ov; i = oi; }
    }
    v = __shfl_sync(0xffffffffu, v, 0);
    i = __shfl_sync(0xffffffffu, i, 0);
}

// ---------------------------------------------------------------------------
// Kernel 1: compact. Block = 64 anchors x 80 classes of one batch.
// conf<=0.55 anchors skipped entirely (product can't exceed threshold).
// Winners staged in smem per class, flushed with one global atomic per class.
// ---------------------------------------------------------------------------
__global__ void __launch_bounds__(256) compact_kernel(
        const float* __restrict__ bb0, const float* __restrict__ cf0, const float* __restrict__ cl0,
        const float* __restrict__ bb1, const float* __restrict__ cf1, const float* __restrict__ cl1,
        const float* __restrict__ bb2, const float* __restrict__ cf2, const float* __restrict__ cl2) {
    __shared__ float4 sbox[CA];
    __shared__ float  sconf[CA];
    __shared__ const float4* sclp[CA];
    __shared__ int s_scnt[NC];
    __shared__ float stage_s[NC * SCAP];
    __shared__ unsigned char stage_a[NC * SCAP];

    int b = blockIdx.y;
    int a0 = blockIdx.x * CA;
    int tid = threadIdx.x;

    if (tid < CA) {
        int n = a0 + tid;
        float cfv = -1.f;
        float4 v = make_float4(0.f, 0.f, 0.f, 0.f);
        const float* cp = cl0;
        int loc = 0;
        if (n < NT) {
            const float* bp;
            const float* fp;
            if (n < GN0)            { bp = bb0; fp = cf0; cp = cl0; loc = b * GN0 + n; }
            else if (n < GN0 + GN1) { bp = bb1; fp = cf1; cp = cl1; loc = b * GN1 + (n - GN0); }
            else                    { bp = bb2; fp = cf2; cp = cl2; loc = b * GN2 + (n - GN0 - GN1); }
            v = reinterpret_cast<const float4*>(bp)[loc];
            v.x = fmaxf(v.x, 0.f); v.y = fmaxf(v.y, 0.f);
            v.z = fmaxf(v.z, 0.f); v.w = fmaxf(v.w, 0.f);
            cfv = fp[loc];
        }
        sbox[tid] = v;
        sconf[tid] = cfv;
        sclp[tid] = reinterpret_cast<const float4*>(cp + (size_t)loc * NC);
    }
    if (tid < NC) s_scnt[tid] = 0;
    __syncthreads();

    #pragma unroll
    for (int it = 0; it < 5; it++) {
        int t = it * 256 + tid;          // 0..1279 = 64 anchors * 20 float4s
        int a = t / 20, q = t % 20;
        float cfv = sconf[a];
        if (cfv > SCORE_T) {
            float4 cv = __ldg(sclp[a] + q);
            int cb = q * 4;
            #pragma unroll
            for (int k = 0; k < 4; k++) {
                float cvk = (k == 0) ? cv.x : (k == 1) ? cv.y : (k == 2) ? cv.z : cv.w;
                float s = __fmul_rn(cfv, cvk);
                if (s > SCORE_T) {
                    int c = cb + k;
                    int p = atomicAdd(&s_scnt[c], 1);
                    if (p < SCAP) {
                        stage_s[c * SCAP + p] = s;
                        stage_a[c * SCAP + p] = (unsigned char)a;
                    } else {  // rare overflow -> direct global
                        int cell = b * NC + c;
                        int g = atomicAdd(&g_cnt[cell], 1);
                        if (g < CAP) {
                            g_cs[(size_t)cell * CAP + g] = s;
                            g_cbox[(size_t)cell * CAP + g] = sbox[a];
                        }
                    }
                }
            }
        }
    }
    __syncthreads();

    int wid = tid >> 5, lane = tid & 31;
    for (int c = wid; c < NC; c += 8) {
        int cnt = min(s_scnt[c], SCAP);
        if (cnt > 0) {
            int cell = b * NC + c;
            int bas = 0;
            if (lane == 0) bas = atomicAdd(&g_cnt[cell], cnt);
            bas = __shfl_sync(0xffffffffu, bas, 0);
            if (lane < cnt) {
                int idx = bas + lane;
                if (idx < CAP) {
                    g_cs[(size_t)cell * CAP + idx] = stage_s[c * SCAP + lane];
                    g_cbox[(size_t)cell * CAP + idx] = sbox[stage_a[c * SCAP + lane]];
                }
            }
        }
    }
}

// ---------------------------------------------------------------------------
// Kernel 2: NMS via exact descending walk. Block(128) per (b,c) cell.
// ---------------------------------------------------------------------------
__global__ void __launch_bounds__(128) nms_kernel() {
    __shared__ int    hist[NBIN];
    __shared__ float  chs[CHUNK];
    __shared__ float4 cbx[CHUNK];
    __shared__ float  smax[NGRP];
    __shared__ float  ka0[KMAX], ka1[KMAX], ka2[KMAX], ka3[KMAX];  // kept canonical y0,x0,y1,x1
    __shared__ int    s_ctl[4];    // 0:newHi 1:chunk cnt 2:keeps 3:emg flag
    __shared__ int    mask[(CAP + 31) / 32];

    int bc = blockIdx.x;
    int tid = threadIdx.x;
    int M = min(g_cnt[bc], CAP);
    const float*  cs = g_cs   + (size_t)bc * CAP;
    const float4* cb = g_cbox + (size_t)bc * CAP;
    int base = bc * KMAX;

    int hiBin = NBIN;
    int keeps = 0;

    while (keeps < KMAX && hiBin > 0) {
        // ---- pass 1: histogram of unconsumed score range ----
        for (int i = tid; i < NBIN; i += 128) hist[i] = 0;
        for (int i = tid; i < CHUNK; i += 128) chs[i] = NEGF;
        if (tid == 0) s_ctl[1] = 0;
        __syncthreads();
        for (int j = tid; j < M; j += 128) {
            int bi = bin_of(cs[j]);
            if (bi < hiBin) atomicAdd(&hist[bi], 1);
        }
        __syncthreads();
        // ---- threshold scan (thread 0) ----
        if (tid == 0) {
            int lo = hiBin;
            while (lo > 0 && hist[lo - 1] == 0) lo--;
            if (lo == 0)                  { s_ctl[0] = 0;      s_ctl[3] = 0; }
            else if (hist[lo - 1] > CHUNK){ s_ctl[0] = lo - 1; s_ctl[3] = 1; }
            else {
                int acc = 0;
                while (lo > 0) { int h = hist[lo - 1]; if (acc + h > CHUNK) break; acc += h; lo--; }
                s_ctl[0] = lo; s_ctl[3] = 0;
            }
        }
        __syncthreads();
        int newHi = s_ctl[0];
        int emg = s_ctl[3];

        if (!emg) {
            if (newHi < hiBin) {
                // ---- pass 2: compact chunk (bins [newHi, hiBin)) ----
                for (int j = tid; j < M; j += 128) {
                    float s = cs[j];
                    int bi = bin_of(s);
                    if (bi >= newHi && bi < hiBin) {
                        int p = atomicAdd(&s_ctl[1], 1);
                        chs[p] = s;
                        cbx[p] = cb[j];
                    }
                }
                __syncthreads();
                int cnt = s_ctl[1];
                int ng = (cnt + 31) >> 5;
                if (tid < NGRP) {
                    float m = NEGF;
                    #pragma unroll 4
                    for (int t = 0; t < 32; t++) m = fmaxf(m, chs[tid * 32 + t]);
                    smax[tid] = m;
                }
                __syncthreads();
                // ---- warp0 walk ----
                if (tid < 32) {
                    int lane = tid;
                    int kp = keeps;
                    while (kp < KMAX) {
                        float gv = (lane < ng) ? smax[lane] : NEGF;
                        int gi = lane;
                        argmax32(gv, gi);
                        if (gv == NEGF) break;
                        int jj = gi * 32 + lane;
                        float sv = chs[jj];
                        int si = jj;
                        argmax32(sv, si);
                        float4 v = cbx[si];
                        float cy0 = fminf(v.x, v.z), cy1 = fmaxf(v.x, v.z);
                        float cx0 = fminf(v.y, v.w), cx1 = fmaxf(v.y, v.w);
                        bool sup = false;
                        if (lane < kp)
                            sup = iou_gt(cy0, cx0, cy1, cx1, ka0[lane], ka1[lane], ka2[lane], ka3[lane]);
                        unsigned supm = __ballot_sync(0xffffffffu, sup);
                        if (lane == 0) chs[si] = NEGF;
                        __syncwarp();
                        float nv = chs[gi * 32 + lane];
                        #pragma unroll
                        for (int o = 16; o; o >>= 1) nv = fmaxf(nv, __shfl_down_sync(0xffffffffu, nv, o));
                        if (lane == 0) smax[gi] = nv;
                        if (supm == 0) {
                            if (lane == 0) {
                                g_kept_score[base + kp] = sv;
                                g_kept_box4[base + kp] = v;
                                ka0[kp] = cy0; ka1[kp] = cx0; ka2[kp] = cy1; ka3[kp] = cx1;
                            }
                            kp++;
                        }
                        __syncwarp();
                    }
                    if (lane == 0) s_ctl[2] = kp;
                }
                __syncthreads();
                keeps = s_ctl[2];
            }
            hiBin = newHi;
        } else {
            // ---- emergency: single bin larger than CHUNK; serial exact ----
            for (int i = tid; i < (CAP + 31) / 32; i += 128) mask[i] = 0;
            __syncthreads();
            if (tid == 0) {
                int kp = keeps;
                while (kp < KMAX) {
                    float ms = NEGF; int mi = -1;
                    for (int j = 0; j < M; j++) {
                        if ((mask[j >> 5] >> (j & 31)) & 1) continue;
                        float s = cs[j];
                        if (bin_of(s) == newHi && s > ms) { ms = s; mi = j; }
                    }
                    if (mi < 0) break;
                    mask[mi >> 5] |= 1u << (mi & 31);
                    float4 v = cb[mi];
                    float cy0 = fminf(v.x, v.z), cy1 = fmaxf(v.x, v.z);
                    float cx0 = fminf(v.y, v.w), cx1 = fmaxf(v.y, v.w);
                    bool sup = false;
                    for (int q = 0; q < kp && !sup; q++)
                        sup = iou_gt(cy0, cx0, cy1, cx1, ka0[q], ka1[q], ka2[q], ka3[q]);
                    if (!sup) {
                        g_kept_score[base + kp] = ms;
                        g_kept_box4[base + kp] = v;
                        ka0[kp] = cy0; ka1[kp] = cx0; ka2[kp] = cy1; ka3[kp] = cx1;
                        kp++;
                    }
                }
                s_ctl[2] = kp;
            }
            __syncthreads();
            keeps = s_ctl[2];
            hiBin = newHi;
        }
    }
    for (int kk = keeps + tid; kk < KMAX; kk += 128) g_kept_score[base + kk] = NEGF;
}

// ---------------------------------------------------------------------------
// Kernel 3: per-batch top-25 across classes; also zeroes g_cnt for next run.
// Output: boxes[B,25,4] | scores[B,25] | cls[B,25] | valid_det[B]
// ---------------------------------------------------------------------------
__global__ void __launch_bounds__(256) topk_kernel(float* __restrict__ out) {
    __shared__ float  s[NC * KMAX];
    __shared__ float4 sb[NC * KMAX];
    __shared__ float  wr_s[8];
    __shared__ int    wr_i[8];
    __shared__ int    cnt;

    int b = blockIdx.x;
    int tid = threadIdx.x;
    for (int j = tid; j < NC * KMAX; j += 256) {
        s[j]  = g_kept_score[b * NC * KMAX + j];
        sb[j] = g_kept_box4[b * NC * KMAX + j];
    }
    if (tid == 0) cnt = 0;
    if (tid < NC) g_cnt[b * NC + tid] = 0;     // reset for next replay
    __syncthreads();

    for (int k = 0; k < KMAX; k++) {
        float ms = NEGF; int mi = 0x7fffffff;
        for (int j = tid; j < NC * KMAX; j += 256) {
            float v = s[j];
            if (v > ms || (v == ms && j < mi)) { ms = v; mi = j; }
        }
        #pragma unroll
        for (int o = 16; o; o >>= 1) {
            float ov = __shfl_down_sync(0xffffffffu, ms, o);
            int   oi = __shfl_down_sync(0xffffffffu, mi, o);
            if (ov > ms || (ov == ms && oi < mi)) { ms = ov; mi = oi; }
        }
        if ((tid & 31) == 0) { wr_s[tid >> 5] = ms; wr_i[tid >> 5] = mi; }
        __syncthreads();
        if (tid == 0) {
            ms = wr_s[0]; mi = wr_i[0];
            #pragma unroll
            for (int w = 1; w < 8; w++) {
                float ov = wr_s[w]; int oi = wr_i[w];
                if (ov > ms || (ov == ms && oi < mi)) { ms = ov; mi = oi; }
            }
            bool valid = ms > SCORE_T;
            out[BN * KMAX * 4 + b * KMAX + k] = valid ? ms : 0.f;
            out[BN * KMAX * 5 + b * KMAX + k] = valid ? (float)(mi / KMAX) : 0.f;
            float4 v = sb[mi];
            out[(b * KMAX + k) * 4 + 0] = valid ? fminf(fmaxf(v.x, 0.f), 1.f) : 0.f;
            out[(b * KMAX + k) * 4 + 1] = valid ? fminf(fmaxf(v.y, 0.f), 1.f) : 0.f;
            out[(b * KMAX + k) * 4 + 2] = valid ? fminf(fmaxf(v.z, 0.f), 1.f) : 0.f;
            out[(b * KMAX + k) * 4 + 3] = valid ? fminf(fmaxf(v.w, 0.f), 1.f) : 0.f;
            s[mi] = NEGF;
            if (valid) cnt++;
        }
        __syncthreads();
    }
    if (tid == 0) out[BN * KMAX * 6 + b] = (float)cnt;
}

// ---------------------------------------------------------------------------
extern "C" void kernel_launch(void* const* d_in, const int* in_sizes, int n_in,
                              void* d_out, int out_size) {
    const float* bb0 = (const float*)d_in[0];
    const float* cf0 = (const float*)d_in[1];
    const float* cl0 = (const float*)d_in[2];
    const float* bb1 = (const float*)d_in[3];
    const float* cf1 = (const float*)d_in[4];
    const float* cl1 = (const float*)d_in[5];
    const float* bb2 = (const float*)d_in[6];
    const float* cf2 = (const float*)d_in[7];
    const float* cl2 = (const float*)d_in[8];

    dim3 cgrid((NT + CA - 1) / CA, BN);
    compact_kernel<<<cgrid, 256>>>(bb0, cf0, cl0, bb1, cf1, cl1, bb2, cf2, cl2);
    nms_kernel<<<NCELL, 128>>>();
    topk_kernel<<<BN, 256>>>((float*)d_out);
}